// round 2
// baseline (speedup 1.0000x reference)
#include <cuda_runtime.h>
#include <math.h>

// Problem constants
#define TT   512
#define BB   256
#define IND  248
#define HID  1024

// Scratch (device globals: allocation-free per harness rules)
__device__ float g_xp[(size_t)TT * BB * HID];   // 512 MB: xproj[t][b][h]
__device__ float g_h[2][BB * HID];              // ping-pong hidden state
__device__ float g_zp[16][TT * BB];             // per-n-tile partial z, deterministic (no atomics)

// ---------------------------------------------------------------------------
// init: zero h(-1). Needed every replay because step t=1 overwrites g_h[0].
// ---------------------------------------------------------------------------
__global__ void init_kernel() {
    int i = blockIdx.x * blockDim.x + threadIdx.x;
    if (i < BB * HID) g_h[0][i] = 0.0f;
}

// ---------------------------------------------------------------------------
// xproj: xp[m][n] = sum_i x[m][i] * W_ih[n][i] + b_ih[n] + b_hh[n]
//   M = T*B = 131072, N = 1024, K = 248
//   Tile: BM=128, BN=64, BK=8; 256 threads; thread tile 8x4
// ---------------------------------------------------------------------------
__global__ void xproj_kernel(const float* __restrict__ x,
                             const float* __restrict__ W_ih,
                             const float* __restrict__ b_ih,
                             const float* __restrict__ b_hh) {
    __shared__ __align__(16) float As[8][128];  // [k][m]
    __shared__ __align__(16) float Ws[8][64];   // [k][n]

    const int bm  = blockIdx.y * 128;
    const int bn  = blockIdx.x * 64;
    const int lid = threadIdx.x;
    const int tx  = lid & 15;   // n: 4 outputs
    const int ty  = lid >> 4;   // m: 8 outputs

    float acc[8][4];
#pragma unroll
    for (int i = 0; i < 8; i++)
#pragma unroll
        for (int j = 0; j < 4; j++) acc[i][j] = 0.0f;

    for (int k0 = 0; k0 < IND; k0 += 8) {
        // Load A tile: 128 rows x 8 k = 256 float4 (one per thread)
        {
            int r = lid >> 1, c4 = (lid & 1) * 4;
            float4 v = *(const float4*)(x + (size_t)(bm + r) * IND + k0 + c4);
            As[c4 + 0][r] = v.x; As[c4 + 1][r] = v.y;
            As[c4 + 2][r] = v.z; As[c4 + 3][r] = v.w;
        }
        // Load W tile: 64 rows x 8 k = 128 float4
        if (lid < 128) {
            int r = lid >> 1, c4 = (lid & 1) * 4;
            float4 v = *(const float4*)(W_ih + (size_t)(bn + r) * IND + k0 + c4);
            Ws[c4 + 0][r] = v.x; Ws[c4 + 1][r] = v.y;
            Ws[c4 + 2][r] = v.z; Ws[c4 + 3][r] = v.w;
        }
        __syncthreads();

#pragma unroll
        for (int k = 0; k < 8; k++) {
            float4 a0 = *(const float4*)&As[k][ty * 8];
            float4 a1 = *(const float4*)&As[k][ty * 8 + 4];
            float4 w  = *(const float4*)&Ws[k][tx * 4];
            float a[8] = {a0.x, a0.y, a0.z, a0.w, a1.x, a1.y, a1.z, a1.w};
            float wv[4] = {w.x, w.y, w.z, w.w};
#pragma unroll
            for (int i = 0; i < 8; i++)
#pragma unroll
                for (int j = 0; j < 4; j++) acc[i][j] += a[i] * wv[j];
        }
        __syncthreads();
    }

    const int n0 = bn + tx * 4;
    float bias[4];
#pragma unroll
    for (int j = 0; j < 4; j++) bias[j] = b_ih[n0 + j] + b_hh[n0 + j];

    const int m0 = bm + ty * 8;
#pragma unroll
    for (int i = 0; i < 8; i++) {
        float* dst = g_xp + (size_t)(m0 + i) * HID + n0;
        *(float4*)dst = make_float4(acc[i][0] + bias[0], acc[i][1] + bias[1],
                                    acc[i][2] + bias[2], acc[i][3] + bias[3]);
    }
}

// ---------------------------------------------------------------------------
// step t: h_new[b][n] = tanh(xp[t][b][n] + sum_k h_prev[b][k] * W_hh[n][k])
//   plus per-tile partial z[t][b] += sum_n h_new[b][n] * W_out[n]
//   Tile: Bb=32, Bn=64, BK=16; grid (16, 8) = 128 CTAs; 256 threads; thread 2x4
// ---------------------------------------------------------------------------
__global__ void step_kernel(int t,
                            const float* __restrict__ W_hh,
                            const float* __restrict__ W_out) {
    __shared__ __align__(16) float hs[16][32];  // [k][b]
    __shared__ __align__(16) float ws[16][64];  // [k][n]

    const int src = t & 1, dst = src ^ 1;
    const int bn  = blockIdx.x * 64;
    const int bb  = blockIdx.y * 32;
    const int lid = threadIdx.x;
    const int tx  = lid & 15;   // n: 4 outputs
    const int ty  = lid >> 4;   // b: 2 outputs

    float acc[2][4];
#pragma unroll
    for (int i = 0; i < 2; i++)
#pragma unroll
        for (int j = 0; j < 4; j++) acc[i][j] = 0.0f;

    const float* __restrict__ hsrc = g_h[src];

    for (int k0 = 0; k0 < HID; k0 += 16) {
        if (lid < 128) {  // h tile: 32 rows x 16 k = 128 float4
            int r = lid >> 2, c4 = (lid & 3) * 4;
            float4 v = *(const float4*)(hsrc + (size_t)(bb + r) * HID + k0 + c4);
            hs[c4 + 0][r] = v.x; hs[c4 + 1][r] = v.y;
            hs[c4 + 2][r] = v.z; hs[c4 + 3][r] = v.w;
        }
        {  // W tile: 64 rows x 16 k = 256 float4
            int r = lid >> 2, c4 = (lid & 3) * 4;
            float4 v = *(const float4*)(W_hh + (size_t)(bn + r) * HID + k0 + c4);
            ws[c4 + 0][r] = v.x; ws[c4 + 1][r] = v.y;
            ws[c4 + 2][r] = v.z; ws[c4 + 3][r] = v.w;
        }
        __syncthreads();

#pragma unroll
        for (int k = 0; k < 16; k++) {
            float2 a = *(const float2*)&hs[k][ty * 2];
            float4 w = *(const float4*)&ws[k][tx * 4];
            acc[0][0] += a.x * w.x; acc[0][1] += a.x * w.y;
            acc[0][2] += a.x * w.z; acc[0][3] += a.x * w.w;
            acc[1][0] += a.y * w.x; acc[1][1] += a.y * w.y;
            acc[1][2] += a.y * w.z; acc[1][3] += a.y * w.w;
        }
        __syncthreads();
    }

    const float* xpt  = g_xp + (size_t)t * BB * HID;
    float*       hdst = g_h[dst];
    const float4 wo   = *(const float4*)(W_out + bn + tx * 4);

#pragma unroll
    for (int i = 0; i < 2; i++) {
        const int b   = bb + ty * 2 + i;
        const int idx = b * HID + bn + tx * 4;
        float4 xv = *(const float4*)(xpt + idx);
        float h0 = tanhf(xv.x + acc[i][0]);
        float h1 = tanhf(xv.y + acc[i][1]);
        float h2 = tanhf(xv.z + acc[i][2]);
        float h3 = tanhf(xv.w + acc[i][3]);
        *(float4*)(hdst + idx) = make_float4(h0, h1, h2, h3);

        float part = h0 * wo.x + h1 * wo.y + h2 * wo.z + h3 * wo.w;
#pragma unroll
        for (int off = 8; off; off >>= 1)
            part += __shfl_xor_sync(0xffffffffu, part, off);
        if (tx == 0) g_zp[blockIdx.x][t * BB + b] = part;
    }
}

// ---------------------------------------------------------------------------
// output scan: o_0 = sigmoid(z_0); o_t = sigmoid(z_t + w_r*o_{t-1} + b_r)
//   one CTA, thread b handles batch element b; out is (B, T) row-major
// ---------------------------------------------------------------------------
__global__ void out_kernel(const float* __restrict__ b_out,
                           const float* __restrict__ w_r,
                           const float* __restrict__ b_r,
                           float* __restrict__ out) {
    const int b = threadIdx.x;
    const float bo = b_out[0], wr = w_r[0], br = b_r[0];
    float o = 0.0f;
    for (int t = 0; t < TT; t++) {
        float z = bo;
#pragma unroll
        for (int p = 0; p < 16; p++) z += g_zp[p][t * BB + b];
        float arg = (t == 0) ? z : (z + wr * o + br);
        o = 1.0f / (1.0f + expf(-arg));
        out[b * TT + t] = o;
    }
}

// ---------------------------------------------------------------------------
// Launch: graph of 515 kernel nodes on the capture stream.
// ---------------------------------------------------------------------------
extern "C" void kernel_launch(void* const* d_in, const int* in_sizes, int n_in,
                              void* d_out, int out_size) {
    const float* x     = (const float*)d_in[0];
    const float* W_ih  = (const float*)d_in[1];
    const float* b_ih  = (const float*)d_in[2];
    const float* W_hh  = (const float*)d_in[3];
    const float* b_hh  = (const float*)d_in[4];
    const float* W_out = (const float*)d_in[5];
    const float* b_out = (const float*)d_in[6];
    const float* w_r   = (const float*)d_in[7];
    const float* b_r   = (const float*)d_in[8];
    float* out = (float*)d_out;

    init_kernel<<<(BB * HID + 255) / 256, 256>>>();
    xproj_kernel<<<dim3(HID / 64, (TT * BB) / 128), 256>>>(x, W_ih, b_ih, b_hh);
    for (int t = 0; t < TT; t++)
        step_kernel<<<dim3(HID / 64, BB / 32), 256>>>(t, W_hh, W_out);
    out_kernel<<<1, 256>>>(b_out, w_r, b_r, out);
}

// round 3
// speedup vs baseline: 1.0005x; 1.0005x over previous
#include <cuda_runtime.h>
#include <math.h>

// Problem constants
#define TT   512
#define BB   256
#define IND  248
#define HID  1024

// Scratch (device globals: allocation-free per harness rules)
__device__ float g_xp[(size_t)TT * BB * HID];   // 512 MB: xproj[t][b][h]
__device__ float g_h[2][BB * HID];              // ping-pong hidden state
__device__ float g_zp[16][TT * BB];             // per-n-tile partial z, deterministic (no atomics)

// ---------------------------------------------------------------------------
// init: zero h(-1). Needed every replay because step t=1 overwrites g_h[0].
// ---------------------------------------------------------------------------
__global__ void init_kernel() {
    int i = blockIdx.x * blockDim.x + threadIdx.x;
    if (i < BB * HID) g_h[0][i] = 0.0f;
}

// ---------------------------------------------------------------------------
// xproj: xp[m][n] = sum_i x[m][i] * W_ih[n][i] + b_ih[n] + b_hh[n]
//   M = T*B = 131072, N = 1024, K = 248
//   Tile: BM=128, BN=64, BK=8; 256 threads; thread tile 8x4
// ---------------------------------------------------------------------------
__global__ void xproj_kernel(const float* __restrict__ x,
                             const float* __restrict__ W_ih,
                             const float* __restrict__ b_ih,
                             const float* __restrict__ b_hh) {
    __shared__ __align__(16) float As[8][128];  // [k][m]
    __shared__ __align__(16) float Ws[8][64];   // [k][n]

    const int bm  = blockIdx.y * 128;
    const int bn  = blockIdx.x * 64;
    const int lid = threadIdx.x;
    const int tx  = lid & 15;   // n: 4 outputs
    const int ty  = lid >> 4;   // m: 8 outputs

    float acc[8][4];
#pragma unroll
    for (int i = 0; i < 8; i++)
#pragma unroll
        for (int j = 0; j < 4; j++) acc[i][j] = 0.0f;

    for (int k0 = 0; k0 < IND; k0 += 8) {
        // Load A tile: 128 rows x 8 k = 256 float4 (one per thread)
        {
            int r = lid >> 1, c4 = (lid & 1) * 4;
            float4 v = *(const float4*)(x + (size_t)(bm + r) * IND + k0 + c4);
            As[c4 + 0][r] = v.x; As[c4 + 1][r] = v.y;
            As[c4 + 2][r] = v.z; As[c4 + 3][r] = v.w;
        }
        // Load W tile: 64 rows x 8 k = 128 float4
        if (lid < 128) {
            int r = lid >> 1, c4 = (lid & 1) * 4;
            float4 v = *(const float4*)(W_ih + (size_t)(bn + r) * IND + k0 + c4);
            Ws[c4 + 0][r] = v.x; Ws[c4 + 1][r] = v.y;
            Ws[c4 + 2][r] = v.z; Ws[c4 + 3][r] = v.w;
        }
        __syncthreads();

#pragma unroll
        for (int k = 0; k < 8; k++) {
            float4 a0 = *(const float4*)&As[k][ty * 8];
            float4 a1 = *(const float4*)&As[k][ty * 8 + 4];
            float4 w  = *(const float4*)&Ws[k][tx * 4];
            float a[8] = {a0.x, a0.y, a0.z, a0.w, a1.x, a1.y, a1.z, a1.w};
            float wv[4] = {w.x, w.y, w.z, w.w};
#pragma unroll
            for (int i = 0; i < 8; i++)
#pragma unroll
                for (int j = 0; j < 4; j++) acc[i][j] += a[i] * wv[j];
        }
        __syncthreads();
    }

    const int n0 = bn + tx * 4;
    float bias[4];
#pragma unroll
    for (int j = 0; j < 4; j++) bias[j] = b_ih[n0 + j] + b_hh[n0 + j];

    const int m0 = bm + ty * 8;
#pragma unroll
    for (int i = 0; i < 8; i++) {
        float* dst = g_xp + (size_t)(m0 + i) * HID + n0;
        *(float4*)dst = make_float4(acc[i][0] + bias[0], acc[i][1] + bias[1],
                                    acc[i][2] + bias[2], acc[i][3] + bias[3]);
    }
}

// ---------------------------------------------------------------------------
// step t: h_new[b][n] = tanh(xp[t][b][n] + sum_k h_prev[b][k] * W_hh[n][k])
//   plus per-tile partial z[t][b] += sum_n h_new[b][n] * W_out[n]
//   Tile: Bb=32, Bn=64, BK=16; grid (16, 8) = 128 CTAs; 256 threads; thread 2x4
// ---------------------------------------------------------------------------
__global__ void step_kernel(int t,
                            const float* __restrict__ W_hh,
                            const float* __restrict__ W_out) {
    __shared__ __align__(16) float hs[16][32];  // [k][b]
    __shared__ __align__(16) float ws[16][64];  // [k][n]

    const int src = t & 1, dst = src ^ 1;
    const int bn  = blockIdx.x * 64;
    const int bb  = blockIdx.y * 32;
    const int lid = threadIdx.x;
    const int tx  = lid & 15;   // n: 4 outputs
    const int ty  = lid >> 4;   // b: 2 outputs

    float acc[2][4];
#pragma unroll
    for (int i = 0; i < 2; i++)
#pragma unroll
        for (int j = 0; j < 4; j++) acc[i][j] = 0.0f;

    const float* __restrict__ hsrc = g_h[src];

    for (int k0 = 0; k0 < HID; k0 += 16) {
        if (lid < 128) {  // h tile: 32 rows x 16 k = 128 float4
            int r = lid >> 2, c4 = (lid & 3) * 4;
            float4 v = *(const float4*)(hsrc + (size_t)(bb + r) * HID + k0 + c4);
            hs[c4 + 0][r] = v.x; hs[c4 + 1][r] = v.y;
            hs[c4 + 2][r] = v.z; hs[c4 + 3][r] = v.w;
        }
        {  // W tile: 64 rows x 16 k = 256 float4
            int r = lid >> 2, c4 = (lid & 3) * 4;
            float4 v = *(const float4*)(W_hh + (size_t)(bn + r) * HID + k0 + c4);
            ws[c4 + 0][r] = v.x; ws[c4 + 1][r] = v.y;
            ws[c4 + 2][r] = v.z; ws[c4 + 3][r] = v.w;
        }
        __syncthreads();

#pragma unroll
        for (int k = 0; k < 16; k++) {
            float2 a = *(const float2*)&hs[k][ty * 2];
            float4 w = *(const float4*)&ws[k][tx * 4];
            acc[0][0] += a.x * w.x; acc[0][1] += a.x * w.y;
            acc[0][2] += a.x * w.z; acc[0][3] += a.x * w.w;
            acc[1][0] += a.y * w.x; acc[1][1] += a.y * w.y;
            acc[1][2] += a.y * w.z; acc[1][3] += a.y * w.w;
        }
        __syncthreads();
    }

    const float* xpt  = g_xp + (size_t)t * BB * HID;
    float*       hdst = g_h[dst];
    const float4 wo   = *(const float4*)(W_out + bn + tx * 4);

#pragma unroll
    for (int i = 0; i < 2; i++) {
        const int b   = bb + ty * 2 + i;
        const int idx = b * HID + bn + tx * 4;
        float4 xv = *(const float4*)(xpt + idx);
        float h0 = tanhf(xv.x + acc[i][0]);
        float h1 = tanhf(xv.y + acc[i][1]);
        float h2 = tanhf(xv.z + acc[i][2]);
        float h3 = tanhf(xv.w + acc[i][3]);
        *(float4*)(hdst + idx) = make_float4(h0, h1, h2, h3);

        float part = h0 * wo.x + h1 * wo.y + h2 * wo.z + h3 * wo.w;
#pragma unroll
        for (int off = 8; off; off >>= 1)
            part += __shfl_xor_sync(0xffffffffu, part, off);
        if (tx == 0) g_zp[blockIdx.x][t * BB + b] = part;
    }
}

// ---------------------------------------------------------------------------
// output scan: o_0 = sigmoid(z_0); o_t = sigmoid(z_t + w_r*o_{t-1} + b_r)
//   one CTA, thread b handles batch element b; out is (B, T) row-major
// ---------------------------------------------------------------------------
__global__ void out_kernel(const float* __restrict__ b_out,
                           const float* __restrict__ w_r,
                           const float* __restrict__ b_r,
                           float* __restrict__ out) {
    const int b = threadIdx.x;
    const float bo = b_out[0], wr = w_r[0], br = b_r[0];
    float o = 0.0f;
    for (int t = 0; t < TT; t++) {
        float z = bo;
#pragma unroll
        for (int p = 0; p < 16; p++) z += g_zp[p][t * BB + b];
        float arg = (t == 0) ? z : (z + wr * o + br);
        o = 1.0f / (1.0f + expf(-arg));
        out[b * TT + t] = o;
    }
}

// ---------------------------------------------------------------------------
// Launch: graph of 515 kernel nodes on the capture stream.
// ---------------------------------------------------------------------------
extern "C" void kernel_launch(void* const* d_in, const int* in_sizes, int n_in,
                              void* d_out, int out_size) {
    const float* x     = (const float*)d_in[0];
    const float* W_ih  = (const float*)d_in[1];
    const float* b_ih  = (const float*)d_in[2];
    const float* W_hh  = (const float*)d_in[3];
    const float* b_hh  = (const float*)d_in[4];
    const float* W_out = (const float*)d_in[5];
    const float* b_out = (const float*)d_in[6];
    const float* w_r   = (const float*)d_in[7];
    const float* b_r   = (const float*)d_in[8];
    float* out = (float*)d_out;

    init_kernel<<<(BB * HID + 255) / 256, 256>>>();
    xproj_kernel<<<dim3(HID / 64, (TT * BB) / 128), 256>>>(x, W_ih, b_ih, b_hh);
    for (int t = 0; t < TT; t++)
        step_kernel<<<dim3(HID / 64, BB / 32), 256>>>(t, W_hh, W_out);
    out_kernel<<<1, 256>>>(b_out, w_r, b_r, out);
}

// round 5
// speedup vs baseline: 2.4318x; 2.4306x over previous
#include <cuda_runtime.h>
#include <cuda_bf16.h>
#include <mma.h>
#include <math.h>
#include <stdint.h>

using namespace nvcuda;
typedef __nv_bfloat16 bf16;

#define TT   512
#define BB   256
#define IND  248
#define KP   256     // padded input dim
#define HID  1024
#define NCTA 128

// ---------------------------------------------------------------------------
// Device globals (allocation-free scratch)
// ---------------------------------------------------------------------------
__device__ float g_xp[(size_t)TT * BB * HID];     // xproj result (fp32), 512 MB
__device__ bf16  g_xh[(size_t)TT * BB * KP];      // x hi (padded)
__device__ bf16  g_xl[(size_t)TT * BB * KP];      // x lo
__device__ bf16  g_wihh[HID * KP];                // W_ih hi (padded)
__device__ bf16  g_wihl[HID * KP];                // W_ih lo
__device__ bf16  g_whhh[HID * HID];               // W_hh hi
__device__ bf16  g_whhl[HID * HID];               // W_hh lo
__device__ bf16  g_hh[2][BB * HID];               // hidden hi, ping-pong
__device__ bf16  g_hl[2][BB * HID];               // hidden lo, ping-pong
__device__ float g_zp[16][TT * BB];               // per-n-block z partials
__device__ float g_zsum[BB * TT];                 // reduced z, [b][t]
__device__ unsigned g_bar;                        // grid barrier counter

// ---------------------------------------------------------------------------
// helpers
// ---------------------------------------------------------------------------
__device__ __forceinline__ uint32_t smem_u32(const void* p) {
    uint32_t a;
    asm("{ .reg .u64 t; cvta.to.shared.u64 t, %1; cvt.u32.u64 %0, t; }" : "=r"(a) : "l"(p));
    return a;
}
__device__ __forceinline__ void cp16_ca(void* s, const void* g) {
    asm volatile("cp.async.ca.shared.global [%0], [%1], 16;" :: "r"(smem_u32(s)), "l"(g) : "memory");
}
__device__ __forceinline__ void cp16_cg(void* s, const void* g) {
    asm volatile("cp.async.cg.shared.global [%0], [%1], 16;" :: "r"(smem_u32(s)), "l"(g) : "memory");
}
#define CP_COMMIT() asm volatile("cp.async.commit_group;" ::: "memory")
#define CP_WAIT0()  asm volatile("cp.async.wait_group 0;" ::: "memory")

__device__ __forceinline__ float fast_tanh(float x) {
    float r;
    asm("tanh.approx.f32 %0, %1;" : "=f"(r) : "f"(x));
    return r;
}

// ---------------------------------------------------------------------------
// init: zero h(-1) hi/lo and barrier
// ---------------------------------------------------------------------------
__global__ void init_kernel() {
    int i = blockIdx.x * blockDim.x + threadIdx.x;   // 32768 threads
    if (i < BB * HID / 8) {
        ((uint4*)g_hh[0])[i] = make_uint4(0, 0, 0, 0);
        ((uint4*)g_hl[0])[i] = make_uint4(0, 0, 0, 0);
    }
    if (i == 0) g_bar = 0;
}

// ---------------------------------------------------------------------------
// prep: hi/lo splits
// ---------------------------------------------------------------------------
__global__ void prep_whh(const float* __restrict__ W_hh) {
    int i = blockIdx.x * blockDim.x + threadIdx.x;   // HID*HID
    float w = W_hh[i];
    bf16 hi = __float2bfloat16(w);
    g_whhh[i] = hi;
    g_whhl[i] = __float2bfloat16(w - __bfloat162float(hi));
}
__global__ void prep_wih(const float* __restrict__ W_ih) {
    int i = blockIdx.x * blockDim.x + threadIdx.x;   // HID*KP
    int row = i >> 8, col = i & 255;
    float w = (col < IND) ? W_ih[row * IND + col] : 0.0f;
    bf16 hi = __float2bfloat16(w);
    g_wihh[i] = hi;
    g_wihl[i] = __float2bfloat16(w - __bfloat162float(hi));
}
__global__ void prep_x(const float* __restrict__ x) {
    size_t i = (size_t)blockIdx.x * blockDim.x + threadIdx.x;  // TT*BB*KP
    size_t row = i >> 8; int col = (int)(i & 255);
    float v = (col < IND) ? x[row * IND + col] : 0.0f;
    bf16 hi = __float2bfloat16(v);
    g_xh[i] = hi;
    g_xl[i] = __float2bfloat16(v - __bfloat162float(hi));
}

// ---------------------------------------------------------------------------
// xproj via wmma: out[m][n] = sum_k x[m][k]*W_ih[n][k] + b_ih[n] + b_hh[n]
//   CTA tile 32m x 64n; warp tile 16x16; K=256 in 8 chunks of 32, hi/lo x3.
// ---------------------------------------------------------------------------
__global__ void __launch_bounds__(256) xproj_tc(const float* __restrict__ b_ih,
                                               const float* __restrict__ b_hh) {
    __shared__ bf16 sAh[2][32][40], sAl[2][32][40];
    __shared__ bf16 sBh[2][64][40], sBl[2][64][40];
    __shared__ float sOut[32][72];

    const int tid = threadIdx.x, wid = tid >> 5;
    const int nb = blockIdx.x, mb = blockIdx.y;       // n-block(64), m-block(32)
    const int wb = wid & 1, wn = wid >> 1;

    wmma::fragment<wmma::accumulator, 16, 16, 16, float> acc;
    wmma::fill_fragment(acc, 0.0f);

    auto issue = [&](int buf, int k0) {
        int r, c8;
        if (tid < 128) {
            r = tid >> 2; c8 = (tid & 3) * 8;
            cp16_ca(&sAh[buf][r][c8], g_xh + (size_t)(mb * 32 + r) * KP + k0 + c8);
        } else {
            int t2 = tid - 128; r = t2 >> 2; c8 = (t2 & 3) * 8;
            cp16_ca(&sAl[buf][r][c8], g_xl + (size_t)(mb * 32 + r) * KP + k0 + c8);
        }
        r = tid >> 2; c8 = (tid & 3) * 8;
        cp16_ca(&sBh[buf][r][c8], g_wihh + (nb * 64 + r) * KP + k0 + c8);
        cp16_ca(&sBl[buf][r][c8], g_wihl + (nb * 64 + r) * KP + k0 + c8);
    };

    issue(0, 0); CP_COMMIT();
    for (int c = 0; c < 8; c++) {
        CP_WAIT0();
        __syncthreads();
        if (c < 7) { issue((c + 1) & 1, (c + 1) * 32); CP_COMMIT(); }
        const int buf = c & 1;
#pragma unroll
        for (int s = 0; s < 32; s += 16) {
            wmma::fragment<wmma::matrix_a, 16, 16, 16, bf16, wmma::row_major> ah, al;
            wmma::fragment<wmma::matrix_b, 16, 16, 16, bf16, wmma::col_major> bh, blf;
            wmma::load_matrix_sync(ah, &sAh[buf][wb * 16][s], 40);
            wmma::load_matrix_sync(al, &sAl[buf][wb * 16][s], 40);
            wmma::load_matrix_sync(bh, &sBh[buf][wn * 16][s], 40);
            wmma::load_matrix_sync(blf, &sBl[buf][wn * 16][s], 40);
            wmma::mma_sync(acc, ah, bh, acc);
            wmma::mma_sync(acc, ah, blf, acc);
            wmma::mma_sync(acc, al, bh, acc);
        }
    }
    __syncthreads();
    wmma::store_matrix_sync(&sOut[wb * 16][wn * 16], acc, 72, wmma::mem_row_major);
    __syncthreads();

    const int ml = tid & 31, grp = tid >> 5;
    const int n0 = nb * 64 + grp * 8;
    float r[8];
#pragma unroll
    for (int j = 0; j < 8; j++)
        r[j] = sOut[ml][grp * 8 + j] + b_ih[n0 + j] + b_hh[n0 + j];
    float* dst = g_xp + (size_t)(mb * 32 + ml) * HID + n0;
    *(float4*)dst       = make_float4(r[0], r[1], r[2], r[3]);
    *(float4*)(dst + 4) = make_float4(r[4], r[5], r[6], r[7]);
}

// ---------------------------------------------------------------------------
// Persistent scan: 128 CTAs = 8 b-blocks(32) x 16 n-blocks(64).
// Per step: acc[32b x 64n] = h_hi*W_hi + h_hi*W_lo + h_lo*W_hi (wmma bf16),
// epilogue tanh + hi/lo h store + fused z partial, then gmem grid barrier.
// ---------------------------------------------------------------------------
__global__ void __launch_bounds__(256, 1) step_tc(const float* __restrict__ W_out) {
    __shared__ bf16 sAh[2][32][40], sAl[2][32][40];
    __shared__ bf16 sBh[2][64][40], sBl[2][64][40];
    __shared__ float sOut[32][72];
    __shared__ float sZ[8][32];
    __shared__ float sWout[64];

    const int tid = threadIdx.x, wid = tid >> 5;
    const int nb = blockIdx.x & 15, bb = blockIdx.x >> 4;
    const int wb = wid & 1, wn = wid >> 1;
    const int bl = tid & 31, grp = tid >> 5;

    if (tid < 64) sWout[tid] = W_out[nb * 64 + tid];
    __syncthreads();

    for (int t = 0; t < TT; t++) {
        const bf16* __restrict__ hh = g_hh[t & 1];
        const bf16* __restrict__ hl = g_hl[t & 1];

        wmma::fragment<wmma::accumulator, 16, 16, 16, float> acc;
        wmma::fill_fragment(acc, 0.0f);

        auto issue = [&](int buf, int k0) {
            int r, c8;
            if (tid < 128) {                       // h hi (must bypass L1: written by other SMs)
                r = tid >> 2; c8 = (tid & 3) * 8;
                cp16_cg(&sAh[buf][r][c8], hh + (bb * 32 + r) * HID + k0 + c8);
            } else {                               // h lo
                int t2 = tid - 128; r = t2 >> 2; c8 = (t2 & 3) * 8;
                cp16_cg(&sAl[buf][r][c8], hl + (bb * 32 + r) * HID + k0 + c8);
            }
            r = tid >> 2; c8 = (tid & 3) * 8;       // weights: constant, L1 ok
            cp16_ca(&sBh[buf][r][c8], g_whhh + (nb * 64 + r) * HID + k0 + c8);
            cp16_ca(&sBl[buf][r][c8], g_whhl + (nb * 64 + r) * HID + k0 + c8);
        };

        issue(0, 0); CP_COMMIT();
        for (int c = 0; c < 32; c++) {
            CP_WAIT0();
            __syncthreads();
            if (c < 31) { issue((c + 1) & 1, (c + 1) * 32); CP_COMMIT(); }
            const int buf = c & 1;
#pragma unroll
            for (int s = 0; s < 32; s += 16) {
                wmma::fragment<wmma::matrix_a, 16, 16, 16, bf16, wmma::row_major> ah, al;
                wmma::fragment<wmma::matrix_b, 16, 16, 16, bf16, wmma::col_major> bh, blf;
                wmma::load_matrix_sync(ah, &sAh[buf][wb * 16][s], 40);
                wmma::load_matrix_sync(al, &sAl[buf][wb * 16][s], 40);
                wmma::load_matrix_sync(bh, &sBh[buf][wn * 16][s], 40);
                wmma::load_matrix_sync(blf, &sBl[buf][wn * 16][s], 40);
                wmma::mma_sync(acc, ah, bh, acc);
                wmma::mma_sync(acc, ah, blf, acc);
                wmma::mma_sync(acc, al, bh, acc);
            }
        }
        __syncthreads();
        wmma::store_matrix_sync(&sOut[wb * 16][wn * 16], acc, 72, wmma::mem_row_major);
        __syncthreads();

        // ---- epilogue: tanh + h hi/lo store + z partial ----
        const int bglob = bb * 32 + bl;
        const int n0 = nb * 64 + grp * 8;
        const float* xpp = g_xp + ((size_t)t * BB + bglob) * HID + n0;
        float4 x1 = __ldg((const float4*)xpp);
        float4 x2 = __ldg((const float4*)(xpp + 4));
        float xv[8] = {x1.x, x1.y, x1.z, x1.w, x2.x, x2.y, x2.z, x2.w};

        bf16 hb[8], lb[8];
        float z = 0.0f;
#pragma unroll
        for (int j = 0; j < 8; j++) {
            float f = fast_tanh(xv[j] + sOut[bl][grp * 8 + j]);
            z += f * sWout[grp * 8 + j];
            bf16 hi = __float2bfloat16(f);
            hb[j] = hi;
            lb[j] = __float2bfloat16(f - __bfloat162float(hi));
        }
        const int dst = (t & 1) ^ 1;
        *(uint4*)(g_hh[dst] + bglob * HID + n0) = *(uint4*)hb;
        *(uint4*)(g_hl[dst] + bglob * HID + n0) = *(uint4*)lb;

        sZ[grp][bl] = z;
        __threadfence();          // h stores visible before barrier arrive
        __syncthreads();
        if (tid < 32) {
            float s = 0.0f;
#pragma unroll
            for (int g = 0; g < 8; g++) s += sZ[g][tid];
            g_zp[nb][t * BB + bb * 32 + tid] = s;
        }
        // ---- grid barrier ----
        if (tid == 0) {
            atomicAdd(&g_bar, 1u);
            const unsigned tgt = (unsigned)NCTA * (unsigned)(t + 1);
            while (*(volatile unsigned*)&g_bar < tgt) { }
        }
        __syncthreads();
    }
}

// ---------------------------------------------------------------------------
// reduce z partials: g_zsum[b][t] = sum_nb g_zp[nb][t*BB+b]
// ---------------------------------------------------------------------------
__global__ void reduce_z() {
    int idx = blockIdx.x * blockDim.x + threadIdx.x;  // t*BB+b, coalesced reads
    int b = idx & 255, t = idx >> 8;
    float s = 0.0f;
#pragma unroll
    for (int p = 0; p < 16; p++) s += g_zp[p][idx];
    g_zsum[b * TT + t] = s;
}

// ---------------------------------------------------------------------------
// output scan: o_0 = sigmoid(z_0); o_t = sigmoid(z_t + w_r*o_{t-1} + b_r)
// ---------------------------------------------------------------------------
__global__ void out_kernel(const float* __restrict__ b_out,
                           const float* __restrict__ w_r,
                           const float* __restrict__ b_r,
                           float* __restrict__ out) {
    const int b = threadIdx.x;
    const float bo = b_out[0], wr = w_r[0], br = b_r[0];
    float o = 0.0f;
    for (int t4 = 0; t4 < TT; t4 += 4) {
        float4 z4 = *(const float4*)(g_zsum + b * TT + t4);
        float zz[4] = {z4.x, z4.y, z4.z, z4.w};
        float oo[4];
#pragma unroll
        for (int j = 0; j < 4; j++) {
            float arg = (t4 + j == 0) ? (zz[j] + bo) : (zz[j] + bo + wr * o + br);
            o = 1.0f / (1.0f + expf(-arg));
            oo[j] = o;
        }
        *(float4*)(out + b * TT + t4) = make_float4(oo[0], oo[1], oo[2], oo[3]);
    }
}

// ---------------------------------------------------------------------------
// Launch
// ---------------------------------------------------------------------------
extern "C" void kernel_launch(void* const* d_in, const int* in_sizes, int n_in,
                              void* d_out, int out_size) {
    const float* x     = (const float*)d_in[0];
    const float* W_ih  = (const float*)d_in[1];
    const float* b_ih  = (const float*)d_in[2];
    const float* W_hh  = (const float*)d_in[3];
    const float* b_hh  = (const float*)d_in[4];
    const float* W_out = (const float*)d_in[5];
    const float* b_out = (const float*)d_in[6];
    const float* w_r   = (const float*)d_in[7];
    const float* b_r   = (const float*)d_in[8];
    float* out = (float*)d_out;

    init_kernel<<<128, 256>>>();
    prep_whh<<<(HID * HID) / 256, 256>>>(W_hh);
    prep_wih<<<(HID * KP) / 256, 256>>>(W_ih);
    prep_x<<<(TT * BB * KP) / 256, 256>>>(x);
    xproj_tc<<<dim3(HID / 64, (TT * BB) / 32), 256>>>(b_ih, b_hh);
    step_tc<<<NCTA, 256>>>(W_out);
    reduce_z<<<(TT * BB) / 256, 256>>>();
    out_kernel<<<1, 256>>>(b_out, w_r, b_r, out);
}

// round 8
// speedup vs baseline: 3.0908x; 1.2710x over previous
#include <cuda_runtime.h>
#include <cuda_bf16.h>
#include <mma.h>
#include <math.h>
#include <stdint.h>

using namespace nvcuda;
typedef __nv_bfloat16 bf16;

#define TT   512
#define BB   256
#define IND  248
#define KP   256     // padded input dim
#define HID  1024
#define NCTA 128
#define CHUNK 128

// ---------------------------------------------------------------------------
// Device globals (allocation-free scratch)
// ---------------------------------------------------------------------------
__device__ float g_xp[(size_t)TT * BB * HID];     // xproj result (fp32)
__device__ bf16  g_xh[(size_t)TT * BB * KP];      // x hi (padded)
__device__ bf16  g_wihh[HID * KP];                // W_ih hi
__device__ bf16  g_wihl[HID * KP];                // W_ih lo
__device__ bf16  g_whhh[HID * HID];               // W_hh hi
__device__ bf16  g_whhl[HID * HID];               // W_hh lo
__device__ bf16  g_hh[2][BB * HID];               // hidden hi, ping-pong
__device__ bf16  g_hl[2][BB * HID];               // hidden lo, ping-pong
__device__ float g_zp[16][TT * BB];               // per-n-block z partials
__device__ float g_zsum[BB * TT];                 // reduced z, [b][t]
__device__ unsigned g_bar;                        // grid barrier counter

// ---------------------------------------------------------------------------
// helpers
// ---------------------------------------------------------------------------
__device__ __forceinline__ uint32_t smem_u32(const void* p) {
    uint32_t a;
    asm("{ .reg .u64 t; cvta.to.shared.u64 t, %1; cvt.u32.u64 %0, t; }" : "=r"(a) : "l"(p));
    return a;
}
__device__ __forceinline__ void cp16_ca(void* s, const void* g) {
    asm volatile("cp.async.ca.shared.global [%0], [%1], 16;" :: "r"(smem_u32(s)), "l"(g) : "memory");
}
__device__ __forceinline__ void cp16_cg(void* s, const void* g) {
    asm volatile("cp.async.cg.shared.global [%0], [%1], 16;" :: "r"(smem_u32(s)), "l"(g) : "memory");
}
#define CP_COMMIT() asm volatile("cp.async.commit_group;" ::: "memory")
#define CP_WAIT0()  asm volatile("cp.async.wait_group 0;" ::: "memory")

__device__ __forceinline__ float fast_tanh(float x) {
    float r;
    asm("tanh.approx.f32 %0, %1;" : "=f"(r) : "f"(x));
    return r;
}

// ---------------------------------------------------------------------------
// init: zero h(-1) hi/lo and barrier
// ---------------------------------------------------------------------------
__global__ void init_kernel() {
    int i = blockIdx.x * blockDim.x + threadIdx.x;
    if (i < BB * HID / 8) {
        ((uint4*)g_hh[0])[i] = make_uint4(0, 0, 0, 0);
        ((uint4*)g_hl[0])[i] = make_uint4(0, 0, 0, 0);
    }
    if (i == 0) g_bar = 0;
}

// ---------------------------------------------------------------------------
// prep: hi/lo splits
// ---------------------------------------------------------------------------
__global__ void prep_whh(const float* __restrict__ W_hh) {
    int i = blockIdx.x * blockDim.x + threadIdx.x;
    float w = W_hh[i];
    bf16 hi = __float2bfloat16(w);
    g_whhh[i] = hi;
    g_whhl[i] = __float2bfloat16(w - __bfloat162float(hi));
}
__global__ void prep_wih(const float* __restrict__ W_ih) {
    int i = blockIdx.x * blockDim.x + threadIdx.x;
    int row = i >> 8, col = i & 255;
    float w = (col < IND) ? W_ih[row * IND + col] : 0.0f;
    bf16 hi = __float2bfloat16(w);
    g_wihh[i] = hi;
    g_wihl[i] = __float2bfloat16(w - __bfloat162float(hi));
}
__global__ void prep_x(const float* __restrict__ x) {
    size_t i = (size_t)blockIdx.x * blockDim.x + threadIdx.x;
    size_t row = i >> 8; int col = (int)(i & 255);
    float v = (col < IND) ? x[row * IND + col] : 0.0f;
    g_xh[i] = __float2bfloat16(v);
}

// ---------------------------------------------------------------------------
// xproj via wmma: out[m][n] = sum_k x_hi[m][k]*(Wih_hi+Wih_lo)[n][k] + biases
//   CTA tile 32m x 128n; 8 warps (2m x 4n), warp tile 16x32; K=256, chunk 64.
// Dynamic smem layout (bytes):
//   sA  [2][32][72]  bf16   @0       (9216)
//   sBh [2][128][72] bf16   @9216    (36864)
//   sBl [2][128][72] bf16   @46080   (36864)
//   sOut[32][136]    f32    @82944   (17408)   total 100352
// ---------------------------------------------------------------------------
__global__ void __launch_bounds__(256) xproj_tc(const float* __restrict__ b_ih,
                                               const float* __restrict__ b_hh) {
    extern __shared__ char smem[];
    bf16 (*sA)[32][72]   = (bf16(*)[32][72])(smem);
    bf16 (*sBh)[128][72] = (bf16(*)[128][72])(smem + 9216);
    bf16 (*sBl)[128][72] = (bf16(*)[128][72])(smem + 46080);
    float (*sOut)[136]   = (float(*)[136])(smem + 82944);

    const int tid = threadIdx.x, wid = tid >> 5;
    const int nb = blockIdx.x, mb = blockIdx.y;       // n-block(128), m-block(32)
    const int wm = wid & 1, wn = wid >> 1;

    wmma::fragment<wmma::accumulator, 16, 16, 16, float> acc[2];
    wmma::fill_fragment(acc[0], 0.0f);
    wmma::fill_fragment(acc[1], 0.0f);

    auto issue = [&](int buf, int k0) {
#pragma unroll
        for (int j = 0; j < 9; j++) {
            const int idx = tid + j * 256;            // 0..2303
            if (idx < 256) {
                const int r = idx >> 3, c8 = (idx & 7) * 8;
                cp16_cg(&sA[buf][r][c8], g_xh + (size_t)(mb * 32 + r) * KP + k0 + c8);
            } else if (idx < 1280) {
                const int i2 = idx - 256, r = i2 >> 3, c8 = (i2 & 7) * 8;
                cp16_ca(&sBh[buf][r][c8], g_wihh + (nb * 128 + r) * KP + k0 + c8);
            } else {
                const int i2 = idx - 1280, r = i2 >> 3, c8 = (i2 & 7) * 8;
                cp16_ca(&sBl[buf][r][c8], g_wihl + (nb * 128 + r) * KP + k0 + c8);
            }
        }
    };

    issue(0, 0); CP_COMMIT();
    for (int c = 0; c < 4; c++) {
        CP_WAIT0();
        __syncthreads();
        if (c < 3) { issue((c + 1) & 1, (c + 1) * 64); CP_COMMIT(); }
        const int buf = c & 1;
#pragma unroll
        for (int s = 0; s < 64; s += 16) {
            wmma::fragment<wmma::matrix_a, 16, 16, 16, bf16, wmma::row_major> ah;
            wmma::load_matrix_sync(ah, &sA[buf][wm * 16][s], 72);
#pragma unroll
            for (int u = 0; u < 2; u++) {
                wmma::fragment<wmma::matrix_b, 16, 16, 16, bf16, wmma::col_major> bh, blf;
                wmma::load_matrix_sync(bh,  &sBh[buf][wn * 32 + u * 16][s], 72);
                wmma::load_matrix_sync(blf, &sBl[buf][wn * 32 + u * 16][s], 72);
                wmma::mma_sync(acc[u], ah, bh, acc[u]);
                wmma::mma_sync(acc[u], ah, blf, acc[u]);
            }
        }
    }
    __syncthreads();
    wmma::store_matrix_sync(&sOut[wm * 16][wn * 32],      acc[0], 136, wmma::mem_row_major);
    wmma::store_matrix_sync(&sOut[wm * 16][wn * 32 + 16], acc[1], 136, wmma::mem_row_major);
    __syncthreads();

    const int ml = tid & 31, grp = tid >> 5;          // grp handles 16 cols
    const int n0 = nb * 128 + grp * 16;
    float r[16];
#pragma unroll
    for (int j = 0; j < 16; j++)
        r[j] = sOut[ml][grp * 16 + j] + b_ih[n0 + j] + b_hh[n0 + j];
    float* dst = g_xp + (size_t)(mb * 32 + ml) * HID + n0;
#pragma unroll
    for (int j = 0; j < 4; j++)
        *(float4*)(dst + 4 * j) = make_float4(r[4*j], r[4*j+1], r[4*j+2], r[4*j+3]);
}

// ---------------------------------------------------------------------------
// Persistent scan: 128 CTAs = 8 bb(32) x 16 nb(64). W_hi slice persistent in
// smem; A(hi/lo) + W_lo streamed in K-chunks of 128, double buffered.
// acc[32b x 64n] = h_hi*W_hi + h_hi*W_lo + h_lo*W_hi.
// Dynamic smem layout (bytes):
//   sW  [64][1032]     bf16  @0       (132096)  persistent W_hi
//   sAh [2][32][136]   bf16  @132096  (17408)
//   sAl [2][32][136]   bf16  @149504  (17408)
//   sWl [2][64][136]   bf16  @166912  (34816)
//   sOut[32][72]       f32   @201728  (9216)
//   sZ  [8][32]        f32   @210944  (1024)
//   sWout[64]          f32   @211968  (256)     total 212224
// ---------------------------------------------------------------------------
__global__ void __launch_bounds__(256, 1) step_tc(const float* __restrict__ W_out) {
    extern __shared__ char smem[];
    bf16 (*sW)[1032]     = (bf16(*)[1032])(smem);
    bf16 (*sAh)[32][136] = (bf16(*)[32][136])(smem + 132096);
    bf16 (*sAl)[32][136] = (bf16(*)[32][136])(smem + 149504);
    bf16 (*sWl)[64][136] = (bf16(*)[64][136])(smem + 166912);
    float (*sOut)[72]    = (float(*)[72])(smem + 201728);
    float (*sZ)[32]      = (float(*)[32])(smem + 210944);
    float* sWout         = (float*)(smem + 211968);

    const int tid = threadIdx.x, wid = tid >> 5;
    const int nb = blockIdx.x & 15, bb = blockIdx.x >> 4;
    const int wb = wid & 1, wn = wid >> 1;
    const int bl = tid & 31, grp = tid >> 5;

    // Load persistent W_hi slice (64 x 1024) once
    for (int i = tid; i < 64 * 128; i += 256) {       // cp16 ops: 128 per row
        const int r = i >> 7, c8 = (i & 127) * 8;
        cp16_ca(&sW[r][c8], g_whhh + (nb * 64 + r) * HID + c8);
    }
    CP_COMMIT();
    if (tid < 64) sWout[tid] = W_out[nb * 64 + tid];
    CP_WAIT0();
    __syncthreads();

    for (int t = 0; t < TT; t++) {
        const bf16* __restrict__ hh = g_hh[t & 1];
        const bf16* __restrict__ hl = g_hl[t & 1];

        wmma::fragment<wmma::accumulator, 16, 16, 16, float> acc;
        wmma::fill_fragment(acc, 0.0f);

        auto issue = [&](int buf, int k0) {
#pragma unroll
            for (int j = 0; j < 8; j++) {
                const int idx = tid + j * 256;        // 0..2047
                if (idx < 512) {                      // h hi: 32 rows x 16 ops
                    const int r = idx >> 4, c8 = (idx & 15) * 8;
                    cp16_cg(&sAh[buf][r][c8], hh + (bb * 32 + r) * HID + k0 + c8);
                } else if (idx < 1024) {              // h lo
                    const int i2 = idx - 512, r = i2 >> 4, c8 = (i2 & 15) * 8;
                    cp16_cg(&sAl[buf][r][c8], hl + (bb * 32 + r) * HID + k0 + c8);
                } else {                              // W lo: 64 rows x 16 ops
                    const int i2 = idx - 1024, r = i2 >> 4, c8 = (i2 & 15) * 8;
                    cp16_ca(&sWl[buf][r][c8], g_whhl + (nb * 64 + r) * HID + k0 + c8);
                }
            }
        };

        float xs[8];
        issue(0, 0); CP_COMMIT();
        for (int c = 0; c < 8; c++) {
            CP_WAIT0();
            __syncthreads();
            if (c < 7) {
                issue((c + 1) & 1, (c + 1) * CHUNK); CP_COMMIT();
            } else {
                // prefetch xp into the last chunk's MMA shadow
                const float* xpp = g_xp + ((size_t)t * BB + bb * 32 + bl) * HID
                                        + nb * 64 + grp * 8;
                float4 x1 = __ldcg((const float4*)xpp);
                float4 x2 = __ldcg((const float4*)(xpp + 4));
                xs[0]=x1.x; xs[1]=x1.y; xs[2]=x1.z; xs[3]=x1.w;
                xs[4]=x2.x; xs[5]=x2.y; xs[6]=x2.z; xs[7]=x2.w;
            }
            const int buf = c & 1, k0 = c * CHUNK;
#pragma unroll
            for (int s = 0; s < CHUNK; s += 16) {
                wmma::fragment<wmma::matrix_a, 16, 16, 16, bf16, wmma::row_major> ah, al;
                wmma::fragment<wmma::matrix_b, 16, 16, 16, bf16, wmma::col_major> bh, blf;
                wmma::load_matrix_sync(ah,  &sAh[buf][wb * 16][s], 136);
                wmma::load_matrix_sync(al,  &sAl[buf][wb * 16][s], 136);
                wmma::load_matrix_sync(bh,  &sW[wn * 16][k0 + s], 1032);
                wmma::load_matrix_sync(blf, &sWl[buf][wn * 16][s], 136);
                wmma::mma_sync(acc, ah, bh, acc);
                wmma::mma_sync(acc, ah, blf, acc);
                wmma::mma_sync(acc, al, bh, acc);
            }
        }
        __syncthreads();
        wmma::store_matrix_sync(&sOut[wb * 16][wn * 16], acc, 72, wmma::mem_row_major);
        __syncthreads();

        // ---- epilogue: tanh + h hi/lo store + z partial ----
        const int bglob = bb * 32 + bl;
        const int n0 = nb * 64 + grp * 8;

        bf16 hb[8], lb[8];
        float z = 0.0f;
#pragma unroll
        for (int j = 0; j < 8; j++) {
            float f = fast_tanh(xs[j] + sOut[bl][grp * 8 + j]);
            z += f * sWout[grp * 8 + j];
            bf16 hi = __float2bfloat16(f);
            hb[j] = hi;
            lb[j] = __float2bfloat16(f - __bfloat162float(hi));
        }
        const int dst = (t & 1) ^ 1;
        *(uint4*)(g_hh[dst] + bglob * HID + n0) = *(uint4*)hb;
        *(uint4*)(g_hl[dst] + bglob * HID + n0) = *(uint4*)lb;

        sZ[grp][bl] = z;
        __threadfence();          // h stores visible before barrier arrive
        __syncthreads();
        if (tid < 32) {
            float s = 0.0f;
#pragma unroll
            for (int g = 0; g < 8; g++) s += sZ[g][tid];
            g_zp[nb][t * BB + bb * 32 + tid] = s;
        }
        // ---- grid barrier ----
        if (tid == 0) {
            atomicAdd(&g_bar, 1u);
            const unsigned tgt = (unsigned)NCTA * (unsigned)(t + 1);
            while (*(volatile unsigned*)&g_bar < tgt) { }
        }
        __syncthreads();
    }
}

// ---------------------------------------------------------------------------
// reduce z partials: g_zsum[b][t] = sum_nb g_zp[nb][t*BB+b]
// ---------------------------------------------------------------------------
__global__ void reduce_z() {
    int idx = blockIdx.x * blockDim.x + threadIdx.x;
    int b = idx & 255, t = idx >> 8;
    float s = 0.0f;
#pragma unroll
    for (int p = 0; p < 16; p++) s += g_zp[p][idx];
    g_zsum[b * TT + t] = s;
}

// ---------------------------------------------------------------------------
// output scan: o_0 = sigmoid(z_0); o_t = sigmoid(z_t + w_r*o_{t-1} + b_r)
// ---------------------------------------------------------------------------
__global__ void out_kernel(const float* __restrict__ b_out,
                           const float* __restrict__ w_r,
                           const float* __restrict__ b_r,
                           float* __restrict__ out) {
    const int b = threadIdx.x;
    const float bo = b_out[0], wr = w_r[0], br = b_r[0];
    float o = 0.0f;
    for (int t4 = 0; t4 < TT; t4 += 4) {
        float4 z4 = *(const float4*)(g_zsum + b * TT + t4);
        float zz[4] = {z4.x, z4.y, z4.z, z4.w};
        float oo[4];
#pragma unroll
        for (int j = 0; j < 4; j++) {
            float arg = (t4 + j == 0) ? (zz[j] + bo) : (zz[j] + bo + wr * o + br);
            o = 1.0f / (1.0f + expf(-arg));
            oo[j] = o;
        }
        *(float4*)(out + b * TT + t4) = make_float4(oo[0], oo[1], oo[2], oo[3]);
    }
}

// ---------------------------------------------------------------------------
// Launch
// ---------------------------------------------------------------------------
extern "C" void kernel_launch(void* const* d_in, const int* in_sizes, int n_in,
                              void* d_out, int out_size) {
    const float* x     = (const float*)d_in[0];
    const float* W_ih  = (const float*)d_in[1];
    const float* b_ih  = (const float*)d_in[2];
    const float* W_hh  = (const float*)d_in[3];
    const float* b_hh  = (const float*)d_in[4];
    const float* W_out = (const float*)d_in[5];
    const float* b_out = (const float*)d_in[6];
    const float* w_r   = (const float*)d_in[7];
    const float* b_r   = (const float*)d_in[8];
    float* out = (float*)d_out;

    cudaFuncSetAttribute(step_tc,  cudaFuncAttributeMaxDynamicSharedMemorySize, 212224);
    cudaFuncSetAttribute(xproj_tc, cudaFuncAttributeMaxDynamicSharedMemorySize, 100352);

    init_kernel<<<128, 256>>>();
    prep_whh<<<(HID * HID) / 256, 256>>>(W_hh);
    prep_wih<<<(HID * KP) / 256, 256>>>(W_ih);
    prep_x<<<(TT * BB * KP) / 256, 256>>>(x);
    xproj_tc<<<dim3(HID / 128, (TT * BB) / 32), 256, 100352>>>(b_ih, b_hh);
    step_tc<<<NCTA, 256, 212224>>>(W_out);
    reduce_z<<<(TT * BB) / 256, 256>>>();
    out_kernel<<<1, 256>>>(b_out, w_r, b_r, out);
}

// round 9
// speedup vs baseline: 5.7320x; 1.8545x over previous
#include <cuda_runtime.h>
#include <cuda_fp16.h>
#include <mma.h>
#include <math.h>
#include <stdint.h>

using namespace nvcuda;

#define TT   512
#define BB   256
#define IND  248
#define KP   256
#define HID  1024
#define NCTA 128
#define CHUNK 256

// ---------------------------------------------------------------------------
// Device globals
// ---------------------------------------------------------------------------
__device__ float  g_xp[(size_t)TT * BB * HID];    // xproj result (fp32)
__device__ __half g_xh[(size_t)TT * BB * KP];     // x (fp16, padded)
__device__ __half g_wihh[HID * KP];               // W_ih hi (fp16)
__device__ __half g_wihl[HID * KP];               // W_ih lo (fp16)
__device__ __half g_whhh[HID * HID];              // W_hh hi (fp16)
__device__ __half g_whhl[HID * HID];              // W_hh lo (fp16)
__device__ __half g_hf[2][BB * HID];              // hidden (fp16), ping-pong
__device__ float  g_zp[32][TT * BB];              // per-n-block z partials
__device__ float  g_zsum[BB * TT];                // reduced z, [b][t]
__device__ unsigned g_barg[4];                    // per-bb-group barrier counters

// ---------------------------------------------------------------------------
// helpers
// ---------------------------------------------------------------------------
__device__ __forceinline__ uint32_t smem_u32(const void* p) {
    uint32_t a;
    asm("{ .reg .u64 t; cvta.to.shared.u64 t, %1; cvt.u32.u64 %0, t; }" : "=r"(a) : "l"(p));
    return a;
}
__device__ __forceinline__ void cp16_ca(void* s, const void* g) {
    asm volatile("cp.async.ca.shared.global [%0], [%1], 16;" :: "r"(smem_u32(s)), "l"(g) : "memory");
}
__device__ __forceinline__ void cp16_cg(void* s, const void* g) {
    asm volatile("cp.async.cg.shared.global [%0], [%1], 16;" :: "r"(smem_u32(s)), "l"(g) : "memory");
}
#define CP_COMMIT() asm volatile("cp.async.commit_group;" ::: "memory")
#define CP_WAIT0()  asm volatile("cp.async.wait_group 0;" ::: "memory")

__device__ __forceinline__ float fast_tanh(float x) {
    float r;
    asm("tanh.approx.f32 %0, %1;" : "=f"(r) : "f"(x));
    return r;
}

// ---------------------------------------------------------------------------
// init: zero h(-1) and barrier counters
// ---------------------------------------------------------------------------
__global__ void init_kernel() {
    int i = blockIdx.x * blockDim.x + threadIdx.x;   // 32768 threads
    if (i < BB * HID / 8) ((uint4*)g_hf[0])[i] = make_uint4(0, 0, 0, 0);
    if (i < 4) g_barg[i] = 0;
}

// ---------------------------------------------------------------------------
// preps (vectorized, 8 elements/thread)
// ---------------------------------------------------------------------------
__global__ void prep_whh(const float* __restrict__ W_hh) {
    int i = blockIdx.x * blockDim.x + threadIdx.x;   // HID*HID/8 threads
    const float* src = W_hh + (size_t)i * 8;
    __half hb[8], lb[8];
#pragma unroll
    for (int j = 0; j < 8; j++) {
        float w = src[j];
        __half hi = __float2half(w);
        hb[j] = hi;
        lb[j] = __float2half(w - __half2float(hi));
    }
    *(uint4*)(g_whhh + (size_t)i * 8) = *(uint4*)hb;
    *(uint4*)(g_whhl + (size_t)i * 8) = *(uint4*)lb;
}
__global__ void prep_wih(const float* __restrict__ W_ih) {
    int i = blockIdx.x * blockDim.x + threadIdx.x;   // HID*32 threads
    int row = i >> 5, g = i & 31;
    __half hb[8], lb[8];
#pragma unroll
    for (int j = 0; j < 8; j++) {
        int col = g * 8 + j;
        float w = (col < IND) ? W_ih[row * IND + col] : 0.0f;
        __half hi = __float2half(w);
        hb[j] = hi;
        lb[j] = __float2half(w - __half2float(hi));
    }
    *(uint4*)(g_wihh + (size_t)row * KP + g * 8) = *(uint4*)hb;
    *(uint4*)(g_wihl + (size_t)row * KP + g * 8) = *(uint4*)lb;
}
__global__ void prep_x(const float* __restrict__ x) {
    size_t i = (size_t)blockIdx.x * blockDim.x + threadIdx.x;  // TT*BB*32 threads
    size_t row = i >> 5; int g = (int)(i & 31);
    __half hb[8];
    if (g < 31) {
        float4 v1 = __ldg((const float4*)(x + row * IND + g * 8));
        float4 v2 = __ldg((const float4*)(x + row * IND + g * 8 + 4));
        float v[8] = {v1.x, v1.y, v1.z, v1.w, v2.x, v2.y, v2.z, v2.w};
#pragma unroll
        for (int j = 0; j < 8; j++) hb[j] = __float2half(v[j]);
    } else {
#pragma unroll
        for (int j = 0; j < 8; j++) hb[j] = __float2half(0.0f);
    }
    *(uint4*)(g_xh + row * KP + g * 8) = *(uint4*)hb;
}

// ---------------------------------------------------------------------------
// xproj via wmma (fp16): out[m][n] = sum_k x[m][k]*(Wih_hi+Wih_lo)[n][k] + biases
//   CTA tile 32m x 128n; 8 warps (2m x 4n), warp tile 16x32; K=256, chunk 64.
// smem: sA[2][32][72] @0 (9216) | sBh[2][128][72] @9216 (36864)
//       sBl[2][128][72] @46080 (36864) | sOut[32][136] f32 @82944 (17408) = 100352
// ---------------------------------------------------------------------------
__global__ void __launch_bounds__(256) xproj_tc(const float* __restrict__ b_ih,
                                               const float* __restrict__ b_hh) {
    extern __shared__ char smem[];
    __half (*sA)[32][72]   = (__half(*)[32][72])(smem);
    __half (*sBh)[128][72] = (__half(*)[128][72])(smem + 9216);
    __half (*sBl)[128][72] = (__half(*)[128][72])(smem + 46080);
    float (*sOut)[136]     = (float(*)[136])(smem + 82944);

    const int tid = threadIdx.x, wid = tid >> 5;
    const int nb = blockIdx.x, mb = blockIdx.y;
    const int wm = wid & 1, wn = wid >> 1;

    wmma::fragment<wmma::accumulator, 16, 16, 16, float> acc[2];
    wmma::fill_fragment(acc[0], 0.0f);
    wmma::fill_fragment(acc[1], 0.0f);

    auto issue = [&](int buf, int k0) {
#pragma unroll
        for (int j = 0; j < 9; j++) {
            const int idx = tid + j * 256;
            if (idx < 256) {
                const int r = idx >> 3, c8 = (idx & 7) * 8;
                cp16_cg(&sA[buf][r][c8], g_xh + (size_t)(mb * 32 + r) * KP + k0 + c8);
            } else if (idx < 1280) {
                const int i2 = idx - 256, r = i2 >> 3, c8 = (i2 & 7) * 8;
                cp16_ca(&sBh[buf][r][c8], g_wihh + (nb * 128 + r) * KP + k0 + c8);
            } else {
                const int i2 = idx - 1280, r = i2 >> 3, c8 = (i2 & 7) * 8;
                cp16_ca(&sBl[buf][r][c8], g_wihl + (nb * 128 + r) * KP + k0 + c8);
            }
        }
    };

    issue(0, 0); CP_COMMIT();
    for (int c = 0; c < 4; c++) {
        CP_WAIT0();
        __syncthreads();
        if (c < 3) { issue((c + 1) & 1, (c + 1) * 64); CP_COMMIT(); }
        const int buf = c & 1;
#pragma unroll
        for (int s = 0; s < 64; s += 16) {
            wmma::fragment<wmma::matrix_a, 16, 16, 16, __half, wmma::row_major> ah;
            wmma::load_matrix_sync(ah, &sA[buf][wm * 16][s], 72);
#pragma unroll
            for (int u = 0; u < 2; u++) {
                wmma::fragment<wmma::matrix_b, 16, 16, 16, __half, wmma::col_major> bh, blf;
                wmma::load_matrix_sync(bh,  &sBh[buf][wn * 32 + u * 16][s], 72);
                wmma::load_matrix_sync(blf, &sBl[buf][wn * 32 + u * 16][s], 72);
                wmma::mma_sync(acc[u], ah, bh, acc[u]);
                wmma::mma_sync(acc[u], ah, blf, acc[u]);
            }
        }
    }
    __syncthreads();
    wmma::store_matrix_sync(&sOut[wm * 16][wn * 32],      acc[0], 136, wmma::mem_row_major);
    wmma::store_matrix_sync(&sOut[wm * 16][wn * 32 + 16], acc[1], 136, wmma::mem_row_major);
    __syncthreads();

    const int ml = tid & 31, grp = tid >> 5;
    const int n0 = nb * 128 + grp * 16;
    float r[16];
#pragma unroll
    for (int j = 0; j < 16; j++)
        r[j] = sOut[ml][grp * 16 + j] + b_ih[n0 + j] + b_hh[n0 + j];
    float* dst = g_xp + (size_t)(mb * 32 + ml) * HID + n0;
#pragma unroll
    for (int j = 0; j < 4; j++)
        *(float4*)(dst + 4 * j) = make_float4(r[4*j], r[4*j+1], r[4*j+2], r[4*j+3]);
}

// ---------------------------------------------------------------------------
// Persistent scan: 128 CTAs = 4 bb(64 rows) x 32 nb(32 cols).
// W_hh slice (32x1024, hi AND lo fp16) fully persistent in smem — no weight
// streaming. Only h (fp16) streamed per step, chunks of 256k, double buffered.
// acc[64b x 32n] = h * (W_hi + W_lo). Per-bb-group (32 CTA) barrier.
// smem layout (bytes):
//   sWh [32][1032] half @0      (66048)
//   sWl [32][1032] half @66048  (66048)
//   sA  [2][64][264] half @132096 (67584)
//   sOut[64][40] f32   @199680  (10240)
//   sWout[32] f32      @209920  (128)    total 210048
// ---------------------------------------------------------------------------
__global__ void __launch_bounds__(256, 1) step_tc(const float* __restrict__ W_out) {
    extern __shared__ char smem[];
    __half (*sWh)[1032]    = (__half(*)[1032])(smem);
    __half (*sWl)[1032]    = (__half(*)[1032])(smem + 66048);
    __half (*sA)[64][264]  = (__half(*)[64][264])(smem + 132096);
    float (*sOut)[40]      = (float(*)[40])(smem + 199680);
    float* sWout           = (float*)(smem + 209920);

    const int tid = threadIdx.x, wid = tid >> 5;
    const int nb = blockIdx.x & 31, bb = blockIdx.x >> 5;
    const int wm = wid & 3, wn = wid >> 2;           // 4 x 2 warp grid

    // epilogue mapping: row r = tid>>2 (64 rows), col group cg = tid&3 (8 cols each)
    const int er = tid >> 2, ec = (tid & 3) * 8;

    // Load persistent W slice (32 x 1024, hi + lo) once
    for (int i = tid; i < 32 * 128; i += 256) {
        const int r = i >> 7, c8 = (i & 127) * 8;
        cp16_ca(&sWh[r][c8], g_whhh + (nb * 32 + r) * HID + c8);
        cp16_ca(&sWl[r][c8], g_whhl + (nb * 32 + r) * HID + c8);
    }
    CP_COMMIT();
    if (tid < 32) sWout[tid] = W_out[nb * 32 + tid];
    CP_WAIT0();
    __syncthreads();

    unsigned* bar = &g_barg[bb];

    for (int t = 0; t < TT; t++) {
        const __half* __restrict__ hsrc = g_hf[t & 1];

        wmma::fragment<wmma::accumulator, 16, 16, 16, float> acc;
        wmma::fill_fragment(acc, 0.0f);

        auto issue = [&](int buf, int k0) {
#pragma unroll
            for (int j = 0; j < 8; j++) {            // 2048 cp16: 64 rows x 32/row
                const int idx = tid + j * 256;
                const int r = idx >> 5, c8 = (idx & 31) * 8;
                cp16_cg(&sA[buf][r][c8], hsrc + (bb * 64 + r) * HID + k0 + c8);
            }
        };

        issue(0, 0); CP_COMMIT();

        // prefetch xp for this step's epilogue (independent of h)
        float xs[8];
        {
            const float* xpp = g_xp + ((size_t)t * BB + bb * 64 + er) * HID + nb * 32 + ec;
            float4 x1 = __ldcg((const float4*)xpp);
            float4 x2 = __ldcg((const float4*)(xpp + 4));
            xs[0]=x1.x; xs[1]=x1.y; xs[2]=x1.z; xs[3]=x1.w;
            xs[4]=x2.x; xs[5]=x2.y; xs[6]=x2.z; xs[7]=x2.w;
        }

        for (int c = 0; c < 4; c++) {
            CP_WAIT0();
            __syncthreads();
            if (c < 3) { issue((c + 1) & 1, (c + 1) * CHUNK); CP_COMMIT(); }
            const int buf = c & 1, k0 = c * CHUNK;
#pragma unroll
            for (int s = 0; s < CHUNK; s += 16) {
                wmma::fragment<wmma::matrix_a, 16, 16, 16, __half, wmma::row_major> ah;
                wmma::fragment<wmma::matrix_b, 16, 16, 16, __half, wmma::col_major> bh, blf;
                wmma::load_matrix_sync(ah,  &sA[buf][wm * 16][s], 264);
                wmma::load_matrix_sync(bh,  &sWh[wn * 16][k0 + s], 1032);
                wmma::load_matrix_sync(blf, &sWl[wn * 16][k0 + s], 1032);
                wmma::mma_sync(acc, ah, bh, acc);
                wmma::mma_sync(acc, ah, blf, acc);
            }
        }
        __syncthreads();
        wmma::store_matrix_sync(&sOut[wm * 16][wn * 16], acc, 40, wmma::mem_row_major);
        __syncthreads();

        // ---- epilogue: tanh + fp16 h store + z partial ----
        const int bglob = bb * 64 + er;
        __half hb[8];
        float z = 0.0f;
#pragma unroll
        for (int j = 0; j < 8; j++) {
            float f = fast_tanh(xs[j] + sOut[er][ec + j]);
            z += f * sWout[ec + j];
            hb[j] = __float2half(f);
        }
        *(uint4*)(g_hf[(t & 1) ^ 1] + bglob * HID + nb * 32 + ec) = *(uint4*)hb;

        // row z: sum across the 4 lanes covering this row
        z += __shfl_xor_sync(0xffffffffu, z, 1);
        z += __shfl_xor_sync(0xffffffffu, z, 2);
        if ((tid & 3) == 0) g_zp[nb][t * BB + bglob] = z;

        // ---- per-bb-group barrier (32 CTAs) ----
        __threadfence();
        __syncthreads();
        if (tid == 0) {
            atomicAdd(bar, 1u);
            const unsigned tgt = 32u * (unsigned)(t + 1);
            while (*(volatile unsigned*)bar < tgt) { }
        }
        __syncthreads();
    }
}

// ---------------------------------------------------------------------------
// reduce z partials: g_zsum[b][t] = sum_nb g_zp[nb][t*BB+b]
// ---------------------------------------------------------------------------
__global__ void reduce_z() {
    int idx = blockIdx.x * blockDim.x + threadIdx.x;
    int b = idx & 255, t = idx >> 8;
    float s = 0.0f;
#pragma unroll
    for (int p = 0; p < 32; p++) s += g_zp[p][idx];
    g_zsum[b * TT + t] = s;
}

// ---------------------------------------------------------------------------
// output scan
// ---------------------------------------------------------------------------
__global__ void out_kernel(const float* __restrict__ b_out,
                           const float* __restrict__ w_r,
                           const float* __restrict__ b_r,
                           float* __restrict__ out) {
    const int b = threadIdx.x;
    const float bo = b_out[0], wr = w_r[0], br = b_r[0];
    float o = 0.0f;
    for (int t4 = 0; t4 < TT; t4 += 4) {
        float4 z4 = *(const float4*)(g_zsum + b * TT + t4);
        float zz[4] = {z4.x, z4.y, z4.z, z4.w};
        float oo[4];
#pragma unroll
        for (int j = 0; j < 4; j++) {
            float arg = (t4 + j == 0) ? (zz[j] + bo) : (zz[j] + bo + wr * o + br);
            o = 1.0f / (1.0f + expf(-arg));
            oo[j] = o;
        }
        *(float4*)(out + b * TT + t4) = make_float4(oo[0], oo[1], oo[2], oo[3]);
    }
}

// ---------------------------------------------------------------------------
// Launch
// ---------------------------------------------------------------------------
extern "C" void kernel_launch(void* const* d_in, const int* in_sizes, int n_in,
                              void* d_out, int out_size) {
    const float* x     = (const float*)d_in[0];
    const float* W_ih  = (const float*)d_in[1];
    const float* b_ih  = (const float*)d_in[2];
    const float* W_hh  = (const float*)d_in[3];
    const float* b_hh  = (const float*)d_in[4];
    const float* W_out = (const float*)d_in[5];
    const float* b_out = (const float*)d_in[6];
    const float* w_r   = (const float*)d_in[7];
    const float* b_r   = (const float*)d_in[8];
    float* out = (float*)d_out;

    cudaFuncSetAttribute(step_tc,  cudaFuncAttributeMaxDynamicSharedMemorySize, 210048);
    cudaFuncSetAttribute(xproj_tc, cudaFuncAttributeMaxDynamicSharedMemorySize, 100352);

    init_kernel<<<128, 256>>>();
    prep_whh<<<(HID * HID / 8) / 256, 256>>>(W_hh);
    prep_wih<<<(HID * 32) / 256, 256>>>(W_ih);
    prep_x<<<(TT * BB * 32) / 256, 256>>>(x);
    xproj_tc<<<dim3(HID / 128, (TT * BB) / 32), 256, 100352>>>(b_ih, b_hh);
    step_tc<<<NCTA, 256, 210048>>>(W_out);
    reduce_z<<<(TT * BB) / 256, 256>>>();
    out_kernel<<<1, 256>>>(b_out, w_r, b_r, out);
}

// round 10
// speedup vs baseline: 7.1339x; 1.2446x over previous
#include <cuda_runtime.h>
#include <cuda_fp16.h>
#include <mma.h>
#include <math.h>
#include <stdint.h>

using namespace nvcuda;

#define TT   512
#define BB   256
#define IND  248
#define KP   256
#define HID  1024
#define NCTA 128
#define CHUNK 512

// ---------------------------------------------------------------------------
// Device globals
// ---------------------------------------------------------------------------
__device__ float  g_xp[(size_t)TT * BB * HID];    // xproj result (fp32)
__device__ __half g_xh[(size_t)TT * BB * KP];     // x (fp16, padded)
__device__ __half g_wih[HID * KP];                // W_ih (fp16)
__device__ __half g_whh[HID * HID];               // W_hh (fp16)
__device__ __half g_hf[2][BB * HID];              // hidden (fp16), ping-pong
__device__ float  g_zp[32][TT * BB];              // per-n-block z partials
__device__ float  g_zsum[BB * TT];                // reduced z, [b][t]
__device__ unsigned g_barg[4 * 32];               // per-bb-group barriers, 128B apart

// ---------------------------------------------------------------------------
// helpers
// ---------------------------------------------------------------------------
__device__ __forceinline__ uint32_t smem_u32(const void* p) {
    uint32_t a;
    asm("{ .reg .u64 t; cvta.to.shared.u64 t, %1; cvt.u32.u64 %0, t; }" : "=r"(a) : "l"(p));
    return a;
}
__device__ __forceinline__ void cp16_ca(void* s, const void* g) {
    asm volatile("cp.async.ca.shared.global [%0], [%1], 16;" :: "r"(smem_u32(s)), "l"(g) : "memory");
}
__device__ __forceinline__ void cp16_cg(void* s, const void* g) {
    asm volatile("cp.async.cg.shared.global [%0], [%1], 16;" :: "r"(smem_u32(s)), "l"(g) : "memory");
}
#define CP_COMMIT() asm volatile("cp.async.commit_group;" ::: "memory")
#define CP_WAIT0()  asm volatile("cp.async.wait_group 0;" ::: "memory")

__device__ __forceinline__ float fast_tanh(float x) {
    float r;
    asm("tanh.approx.f32 %0, %1;" : "=f"(r) : "f"(x));
    return r;
}

// ---------------------------------------------------------------------------
// init: zero h(-1) and barrier counters
// ---------------------------------------------------------------------------
__global__ void init_kernel() {
    int i = blockIdx.x * blockDim.x + threadIdx.x;
    if (i < BB * HID / 8) ((uint4*)g_hf[0])[i] = make_uint4(0, 0, 0, 0);
    if (i < 4 * 32) g_barg[i] = 0;
}

// ---------------------------------------------------------------------------
// preps (vectorized, 8 elements/thread)
// ---------------------------------------------------------------------------
__global__ void prep_whh(const float* __restrict__ W_hh) {
    int i = blockIdx.x * blockDim.x + threadIdx.x;   // HID*HID/8 threads
    const float* src = W_hh + (size_t)i * 8;
    __half hb[8];
#pragma unroll
    for (int j = 0; j < 8; j++) hb[j] = __float2half(src[j]);
    *(uint4*)(g_whh + (size_t)i * 8) = *(uint4*)hb;
}
__global__ void prep_wih(const float* __restrict__ W_ih) {
    int i = blockIdx.x * blockDim.x + threadIdx.x;   // HID*32 threads
    int row = i >> 5, g = i & 31;
    __half hb[8];
#pragma unroll
    for (int j = 0; j < 8; j++) {
        int col = g * 8 + j;
        hb[j] = __float2half((col < IND) ? W_ih[row * IND + col] : 0.0f);
    }
    *(uint4*)(g_wih + (size_t)row * KP + g * 8) = *(uint4*)hb;
}
__global__ void prep_x(const float* __restrict__ x) {
    size_t i = (size_t)blockIdx.x * blockDim.x + threadIdx.x;  // TT*BB*32 threads
    size_t row = i >> 5; int g = (int)(i & 31);
    __half hb[8];
    if (g < 31) {
        float4 v1 = __ldg((const float4*)(x + row * IND + g * 8));
        float4 v2 = __ldg((const float4*)(x + row * IND + g * 8 + 4));
        float v[8] = {v1.x, v1.y, v1.z, v1.w, v2.x, v2.y, v2.z, v2.w};
#pragma unroll
        for (int j = 0; j < 8; j++) hb[j] = __float2half(v[j]);
    } else {
#pragma unroll
        for (int j = 0; j < 8; j++) hb[j] = __float2half(0.0f);
    }
    *(uint4*)(g_xh + row * KP + g * 8) = *(uint4*)hb;
}

// ---------------------------------------------------------------------------
// xproj via wmma (fp16, single term): out = x @ W_ih^T + b_ih + b_hh
//   CTA tile 32m x 128n; 8 warps (2m x 4n); K=256 in 4 chunks of 64.
// smem: sA[2][32][72] @0 (9216) | sB[2][128][72] @9216 (36864)
//       sOut[32][136] f32 @46080 (17408) = 63488
// ---------------------------------------------------------------------------
__global__ void __launch_bounds__(256) xproj_tc(const float* __restrict__ b_ih,
                                               const float* __restrict__ b_hh) {
    extern __shared__ char smem[];
    __half (*sA)[32][72]  = (__half(*)[32][72])(smem);
    __half (*sB)[128][72] = (__half(*)[128][72])(smem + 9216);
    float (*sOut)[136]    = (float(*)[136])(smem + 46080);

    const int tid = threadIdx.x, wid = tid >> 5;
    const int nb = blockIdx.x, mb = blockIdx.y;
    const int wm = wid & 1, wn = wid >> 1;

    wmma::fragment<wmma::accumulator, 16, 16, 16, float> acc[2];
    wmma::fill_fragment(acc[0], 0.0f);
    wmma::fill_fragment(acc[1], 0.0f);

    auto issue = [&](int buf, int k0) {
#pragma unroll
        for (int j = 0; j < 5; j++) {
            const int idx = tid + j * 256;            // 0..1279
            if (idx < 256) {
                const int r = idx >> 3, c8 = (idx & 7) * 8;
                cp16_cg(&sA[buf][r][c8], g_xh + (size_t)(mb * 32 + r) * KP + k0 + c8);
            } else if (idx < 1280) {
                const int i2 = idx - 256, r = i2 >> 3, c8 = (i2 & 7) * 8;
                cp16_ca(&sB[buf][r][c8], g_wih + (size_t)(nb * 128 + r) * KP + k0 + c8);
            }
        }
    };

    issue(0, 0); CP_COMMIT();
    for (int c = 0; c < 4; c++) {
        CP_WAIT0();
        __syncthreads();
        if (c < 3) { issue((c + 1) & 1, (c + 1) * 64); CP_COMMIT(); }
        const int buf = c & 1;
#pragma unroll
        for (int s = 0; s < 64; s += 16) {
            wmma::fragment<wmma::matrix_a, 16, 16, 16, __half, wmma::row_major> ah;
            wmma::load_matrix_sync(ah, &sA[buf][wm * 16][s], 72);
#pragma unroll
            for (int u = 0; u < 2; u++) {
                wmma::fragment<wmma::matrix_b, 16, 16, 16, __half, wmma::col_major> bh;
                wmma::load_matrix_sync(bh, &sB[buf][wn * 32 + u * 16][s], 72);
                wmma::mma_sync(acc[u], ah, bh, acc[u]);
            }
        }
    }
    __syncthreads();
    wmma::store_matrix_sync(&sOut[wm * 16][wn * 32],      acc[0], 136, wmma::mem_row_major);
    wmma::store_matrix_sync(&sOut[wm * 16][wn * 32 + 16], acc[1], 136, wmma::mem_row_major);
    __syncthreads();

    const int ml = tid & 31, grp = tid >> 5;
    const int n0 = nb * 128 + grp * 16;
    float r[16];
#pragma unroll
    for (int j = 0; j < 16; j++)
        r[j] = sOut[ml][grp * 16 + j] + b_ih[n0 + j] + b_hh[n0 + j];
    float* dst = g_xp + (size_t)(mb * 32 + ml) * HID + n0;
#pragma unroll
    for (int j = 0; j < 4; j++)
        *(float4*)(dst + 4 * j) = make_float4(r[4*j], r[4*j+1], r[4*j+2], r[4*j+3]);
}

// ---------------------------------------------------------------------------
// Persistent scan: 128 CTAs = 4 bb(64 rows) x 32 nb(32 cols).
// W_hh slice (32x1024 fp16) persistent in smem; single MMA term.
// h (fp16) streamed per step in 2 chunks of 512, double buffered.
// smem layout (bytes):
//   sW  [32][1032]  half @0      (66048)   persistent W
//   sA  [2][64][520] half @66048 (133120)
//   sOut[64][40]    f32 @199168  (10240)
//   sWout[32]       f32 @209408  (128)    total 209536
// ---------------------------------------------------------------------------
__global__ void __launch_bounds__(256, 1) step_tc(const float* __restrict__ W_out) {
    extern __shared__ char smem[];
    __half (*sW)[1032]    = (__half(*)[1032])(smem);
    __half (*sA)[64][520] = (__half(*)[64][520])(smem + 66048);
    float (*sOut)[40]     = (float(*)[40])(smem + 199168);
    float* sWout          = (float*)(smem + 209408);

    const int tid = threadIdx.x, wid = tid >> 5;
    const int nb = blockIdx.x & 31, bb = blockIdx.x >> 5;
    const int wm = wid & 3, wn = wid >> 2;           // 4m x 2n warp grid
    const int er = tid >> 2, ec = (tid & 3) * 8;     // epilogue: row, col-group

    // Load persistent W slice (32 x 1024) once
    for (int i = tid; i < 32 * 128; i += 256) {
        const int r = i >> 7, c8 = (i & 127) * 8;
        cp16_ca(&sW[r][c8], g_whh + (size_t)(nb * 32 + r) * HID + c8);
    }
    CP_COMMIT();
    if (tid < 32) sWout[tid] = W_out[nb * 32 + tid];
    CP_WAIT0();
    __syncthreads();

    unsigned* bar = &g_barg[bb * 32];

    for (int t = 0; t < TT; t++) {
        const __half* __restrict__ hsrc = g_hf[t & 1];

        wmma::fragment<wmma::accumulator, 16, 16, 16, float> acc;
        wmma::fill_fragment(acc, 0.0f);

        auto issue = [&](int buf, int k0) {
#pragma unroll
            for (int j = 0; j < 16; j++) {           // 4096 cp16: 64 rows x 64/row
                const int idx = tid + j * 256;
                const int r = idx >> 6, c8 = (idx & 63) * 8;
                cp16_cg(&sA[buf][r][c8], hsrc + (size_t)(bb * 64 + r) * HID + k0 + c8);
            }
        };

        issue(0, 0); CP_COMMIT();

        // prefetch xp for this step's epilogue (independent of h)
        float xs[8];
        {
            const float* xpp = g_xp + ((size_t)t * BB + bb * 64 + er) * HID + nb * 32 + ec;
            float4 x1 = __ldcg((const float4*)xpp);
            float4 x2 = __ldcg((const float4*)(xpp + 4));
            xs[0]=x1.x; xs[1]=x1.y; xs[2]=x1.z; xs[3]=x1.w;
            xs[4]=x2.x; xs[5]=x2.y; xs[6]=x2.z; xs[7]=x2.w;
        }

#pragma unroll
        for (int c = 0; c < 2; c++) {
            CP_WAIT0();
            __syncthreads();
            if (c == 0) { issue(1, CHUNK); CP_COMMIT(); }
            const int k0 = c * CHUNK;
#pragma unroll
            for (int s = 0; s < CHUNK; s += 16) {
                wmma::fragment<wmma::matrix_a, 16, 16, 16, __half, wmma::row_major> ah;
                wmma::fragment<wmma::matrix_b, 16, 16, 16, __half, wmma::col_major> bh;
                wmma::load_matrix_sync(ah, &sA[c][wm * 16][s], 520);
                wmma::load_matrix_sync(bh, &sW[wn * 16][k0 + s], 1032);
                wmma::mma_sync(acc, ah, bh, acc);
            }
        }
        __syncthreads();
        wmma::store_matrix_sync(&sOut[wm * 16][wn * 16], acc, 40, wmma::mem_row_major);
        __syncthreads();

        // ---- epilogue: tanh + fp16 h store + z partial ----
        const int bglob = bb * 64 + er;
        __half hb[8];
        float z = 0.0f;
#pragma unroll
        for (int j = 0; j < 8; j++) {
            float f = fast_tanh(xs[j] + sOut[er][ec + j]);
            z += f * sWout[ec + j];
            hb[j] = __float2half(f);
        }
        *(uint4*)(g_hf[(t & 1) ^ 1] + (size_t)bglob * HID + nb * 32 + ec) = *(uint4*)hb;

        z += __shfl_xor_sync(0xffffffffu, z, 1);
        z += __shfl_xor_sync(0xffffffffu, z, 2);
        if ((tid & 3) == 0) g_zp[nb][t * BB + bglob] = z;

        // ---- per-bb-group barrier (32 CTAs) ----
        __threadfence();
        __syncthreads();
        if (tid == 0) {
            atomicAdd(bar, 1u);
            const unsigned tgt = 32u * (unsigned)(t + 1);
            while (*(volatile unsigned*)bar < tgt) { }
        }
        __syncthreads();
    }
}

// ---------------------------------------------------------------------------
// reduce z partials: g_zsum[b][t] = sum_nb g_zp[nb][t*BB+b]
// ---------------------------------------------------------------------------
__global__ void reduce_z() {
    int idx = blockIdx.x * blockDim.x + threadIdx.x;
    int b = idx & 255, t = idx >> 8;
    float s = 0.0f;
#pragma unroll
    for (int p = 0; p < 32; p++) s += g_zp[p][idx];
    g_zsum[b * TT + t] = s;
}

// ---------------------------------------------------------------------------
// output scan
// ---------------------------------------------------------------------------
__global__ void out_kernel(const float* __restrict__ b_out,
                           const float* __restrict__ w_r,
                           const float* __restrict__ b_r,
                           float* __restrict__ out) {
    const int b = threadIdx.x;
    const float bo = b_out[0], wr = w_r[0], br = b_r[0];
    float o = 0.0f;
    for (int t4 = 0; t4 < TT; t4 += 4) {
        float4 z4 = *(const float4*)(g_zsum + b * TT + t4);
        float zz[4] = {z4.x, z4.y, z4.z, z4.w};
        float oo[4];
#pragma unroll
        for (int j = 0; j < 4; j++) {
            float arg = (t4 + j == 0) ? (zz[j] + bo) : (zz[j] + bo + wr * o + br);
            o = 1.0f / (1.0f + expf(-arg));
            oo[j] = o;
        }
        *(float4*)(out + b * TT + t4) = make_float4(oo[0], oo[1], oo[2], oo[3]);
    }
}

// ---------------------------------------------------------------------------
// Launch
// ---------------------------------------------------------------------------
extern "C" void kernel_launch(void* const* d_in, const int* in_sizes, int n_in,
                              void* d_out, int out_size) {
    const float* x     = (const float*)d_in[0];
    const float* W_ih  = (const float*)d_in[1];
    const float* b_ih  = (const float*)d_in[2];
    const float* W_hh  = (const float*)d_in[3];
    const float* b_hh  = (const float*)d_in[4];
    const float* W_out = (const float*)d_in[5];
    const float* b_out = (const float*)d_in[6];
    const float* w_r   = (const float*)d_in[7];
    const float* b_r   = (const float*)d_in[8];
    float* out = (float*)d_out;

    cudaFuncSetAttribute(step_tc,  cudaFuncAttributeMaxDynamicSharedMemorySize, 209536);
    cudaFuncSetAttribute(xproj_tc, cudaFuncAttributeMaxDynamicSharedMemorySize, 63488);

    init_kernel<<<128, 256>>>();
    prep_whh<<<(HID * HID / 8) / 256, 256>>>(W_hh);
    prep_wih<<<(HID * 32) / 256, 256>>>(W_ih);
    prep_x<<<(TT * BB * 32) / 256, 256>>>(x);
    xproj_tc<<<dim3(HID / 128, (TT * BB) / 32), 256, 63488>>>(b_ih, b_hh);
    step_tc<<<NCTA, 256, 209536>>>(W_out);
    reduce_z<<<(TT * BB) / 256, 256>>>();
    out_kernel<<<1, 256>>>(b_out, w_r, b_r, out);
}